// round 2
// baseline (speedup 1.0000x reference)
#include <cuda_runtime.h>
#include <cstdint>
#include <cstddef>

// Binarized 6-layer MLP, exact integer formulation.
//   dot(sign(a), sign(w)) = K - 2*popc(xor(bits_a, bits_w))   (bit = 1 iff value < 0)
//   BatchNorm sign computed exactly in double (mean = int_sum / 2^14 is exact).
// Pipeline: pack_x -> [gemm_popc -> stats -> params -> pack_act] x5 -> gemm_popc(final fp32)

#define MB 16384

// ---------------- static device scratch (no allocations allowed) ----------------
__device__ __align__(16) unsigned g_act0[MB * 128];        // 8 MB  (layer 1/3/5 input bits)
__device__ __align__(16) unsigned g_act1[MB * 16];         // 1 MB  (layer 2/4/6 input bits)
__device__ __align__(16) unsigned g_wb[6][64000];          // packed weight bits per layer
__device__ int                    g_sb[6][512];            // sign(bias) in {-1,+1}
__device__ short                  g_aout[(size_t)MB * 512];// integer pre-activations
__device__ int                    g_sum[512];
__device__ unsigned long long     g_sum2[512];
__device__ double                 g_mean[512];
__device__ double                 g_scale[512];            // invstd * gamma  (>0 when gamma>0)
__device__ double                 g_shift[512];            // beta

// ---------------- pack float sign bits: bit = (v < 0) ----------------
__global__ void pack_sign_kernel(const float* __restrict__ src, unsigned* __restrict__ dst,
                                 int R, int C, int KW) {
    int warp = (int)((blockIdx.x * blockDim.x + threadIdx.x) >> 5);
    int lane = threadIdx.x & 31;
    if (warp >= R * KW) return;
    int row = warp / KW;
    int word = warp - row * KW;
    int col = word * 32 + lane;
    float v = (col < C) ? src[(size_t)row * C + col] : 0.0f;  // pad bit = 0 (matches weight pad)
    unsigned mask = __ballot_sync(0xffffffffu, v < 0.0f);
    if (lane == 0) dst[(size_t)row * KW + word] = mask;
}

__global__ void pack_b_kernel(const float* __restrict__ b, int* __restrict__ sb, int N) {
    int j = blockIdx.x * blockDim.x + threadIdx.x;
    if (j < N) sb[j] = (b[j] < 0.0f) ? -1 : 1;
}

__global__ void zero_stats_kernel(int N) {
    int j = blockIdx.x * blockDim.x + threadIdx.x;
    if (j < N) { g_sum[j] = 0; g_sum2[j] = 0ull; }
}

// ---------------- xor-popcount GEMM: 64x64 tile, 256 threads, 4x4 per thread ----------------
template <bool FINAL>
__global__ void __launch_bounds__(256)
gemm_popc_kernel(const unsigned* __restrict__ abits, const unsigned* __restrict__ bbits,
                 const int* __restrict__ sb, short* __restrict__ aout,
                 float* __restrict__ fout, int N, int K, int KW) {
    __shared__ unsigned As[64][16];   // [row][word]  (A loads broadcast across tx)
    __shared__ unsigned Bs[16][64];   // [word][col]  (vector LDS.128 across cols)

    const int tx = threadIdx.x & 15;
    const int ty = threadIdx.x >> 4;
    const int row0 = blockIdx.y * 64;
    const int col0 = blockIdx.x * 64;

    int acc[4][4];
#pragma unroll
    for (int i = 0; i < 4; i++)
#pragma unroll
        for (int j = 0; j < 4; j++) acc[i][j] = 0;

    const int nchunks = (KW + 15) >> 4;
    for (int ch = 0; ch < nchunks; ch++) {
        const int w0 = ch * 16;
        // load A tile: 64 rows x 16 words, lane-fast over words (coalesced)
        for (int idx = threadIdx.x; idx < 64 * 16; idx += 256) {
            int r = idx >> 4, w = idx & 15;
            unsigned v = 0;
            if (w0 + w < KW) v = abits[(size_t)(row0 + r) * KW + w0 + w];
            As[r][w] = v;
        }
        // load B tile transposed: Bs[word][col]
        for (int idx = threadIdx.x; idx < 64 * 16; idx += 256) {
            int c = idx & 63, w = idx >> 6;
            unsigned v = 0;
            int col = col0 + c;
            if (col < N && w0 + w < KW) v = bbits[(size_t)col * KW + w0 + w];
            Bs[w][c] = v;
        }
        __syncthreads();
#pragma unroll
        for (int w = 0; w < 16; w++) {
            unsigned a0 = As[ty * 4 + 0][w];
            unsigned a1 = As[ty * 4 + 1][w];
            unsigned a2 = As[ty * 4 + 2][w];
            unsigned a3 = As[ty * 4 + 3][w];
            uint4 bv = *(const uint4*)&Bs[w][tx * 4];
            acc[0][0] += __popc(a0 ^ bv.x); acc[0][1] += __popc(a0 ^ bv.y);
            acc[0][2] += __popc(a0 ^ bv.z); acc[0][3] += __popc(a0 ^ bv.w);
            acc[1][0] += __popc(a1 ^ bv.x); acc[1][1] += __popc(a1 ^ bv.y);
            acc[1][2] += __popc(a1 ^ bv.z); acc[1][3] += __popc(a1 ^ bv.w);
            acc[2][0] += __popc(a2 ^ bv.x); acc[2][1] += __popc(a2 ^ bv.y);
            acc[2][2] += __popc(a2 ^ bv.z); acc[2][3] += __popc(a2 ^ bv.w);
            acc[3][0] += __popc(a3 ^ bv.x); acc[3][1] += __popc(a3 ^ bv.y);
            acc[3][2] += __popc(a3 ^ bv.z); acc[3][3] += __popc(a3 ^ bv.w);
        }
        __syncthreads();
    }

#pragma unroll
    for (int i = 0; i < 4; i++) {
        int row = row0 + ty * 4 + i;
#pragma unroll
        for (int j = 0; j < 4; j++) {
            int col = col0 + tx * 4 + j;
            if (col < N) {
                int v = K - 2 * acc[i][j] + sb[col];
                if (FINAL) fout[(size_t)row * N + col] = (float)v;
                else       aout[(size_t)row * N + col] = (short)v;
            }
        }
    }
}

// ---------------- per-column sums over the batch ----------------
__global__ void stats_kernel(const short* __restrict__ a, int N) {
    const int r0 = blockIdx.x * 128;
    for (int c = threadIdx.x; c < N; c += 256) {
        int s = 0;
        long long s2 = 0;
        for (int r = 0; r < 128; r++) {
            int v = a[(size_t)(r0 + r) * N + c];
            s += v;
            s2 += (long long)(v * v);   // v*v <= ~1.68e7 fits int
        }
        atomicAdd(&g_sum[c], s);
        atomicAdd(&g_sum2[c], (unsigned long long)s2);
    }
}

__global__ void params_kernel(const float* __restrict__ gam, const float* __restrict__ bet, int N) {
    int j = blockIdx.x * blockDim.x + threadIdx.x;
    if (j >= N) return;
    double mean = (double)g_sum[j] / 16384.0;                       // exact
    double var  = (double)(long long)g_sum2[j] / 16384.0 - mean * mean;
    double invstd = 1.0 / sqrt(var + 1e-5);
    g_mean[j]  = mean;
    g_scale[j] = invstd * (double)gam[j];
    g_shift[j] = (double)bet[j];
}

// ---------------- pack next-layer activation sign bits (BN + Hardtanh fold to sign) ----------------
__global__ void pack_act_kernel(const short* __restrict__ a, unsigned* __restrict__ dst,
                                int C, int KW) {
    int warp = (int)((blockIdx.x * blockDim.x + threadIdx.x) >> 5);
    int lane = threadIdx.x & 31;
    if (warp >= MB * KW) return;
    int row = warp / KW;
    int word = warp - row * KW;
    int col = word * 32 + lane;
    bool neg = false;
    if (col < C) {
        double y = ((double)a[(size_t)row * C + col] - g_mean[col]) * g_scale[col] + g_shift[col];
        neg = (y < 0.0);   // y >= 0 -> +1 (bit 0), matches binarize(t>=0 -> +1)
    }
    unsigned mask = __ballot_sync(0xffffffffu, neg);
    if (lane == 0) dst[(size_t)row * KW + word] = mask;
}

// ---------------- host orchestration ----------------
extern "C" void kernel_launch(void* const* d_in, const int* in_sizes, int n_in,
                              void* d_out, int out_size) {
    (void)in_sizes; (void)n_in; (void)out_size;
    static const int LK[6]  = {4096, 500, 400, 350, 300, 300};
    static const int LN[6]  = {500, 400, 350, 300, 300, 35};
    static const int LKW[6] = {128, 16, 13, 11, 10, 10};

    const float* x = (const float*)d_in[0];
    const float* W[6]; const float* bb[6]; const float* gam[5]; const float* bet[5];
    for (int l = 0; l < 5; l++) {
        W[l]   = (const float*)d_in[1 + 4 * l];
        bb[l]  = (const float*)d_in[2 + 4 * l];
        gam[l] = (const float*)d_in[3 + 4 * l];
        bet[l] = (const float*)d_in[4 + 4 * l];
    }
    W[5]  = (const float*)d_in[21];
    bb[5] = (const float*)d_in[22];

    unsigned *act0, *act1, *wb;
    int *sb;
    short *aout;
    cudaGetSymbolAddress((void**)&act0, g_act0);
    cudaGetSymbolAddress((void**)&act1, g_act1);
    cudaGetSymbolAddress((void**)&wb,   g_wb);
    cudaGetSymbolAddress((void**)&sb,   g_sb);
    cudaGetSymbolAddress((void**)&aout, g_aout);

    // pack input x -> act0 bits
    {
        int nwarps = MB * 128;
        pack_sign_kernel<<<(nwarps + 7) / 8, 256>>>(x, act0, MB, 4096, 128);
    }
    // pack all weights + biases
    for (int l = 0; l < 6; l++) {
        int nwarps = LN[l] * LKW[l];
        pack_sign_kernel<<<(nwarps + 7) / 8, 256>>>(W[l], wb + (size_t)l * 64000,
                                                    LN[l], LK[l], LKW[l]);
        pack_b_kernel<<<(LN[l] + 255) / 256, 256>>>(bb[l], sb + l * 512, LN[l]);
    }

    unsigned* actIn = act0;
    for (int l = 0; l < 5; l++) {
        const int N = LN[l], K = LK[l], KW = LKW[l];
        zero_stats_kernel<<<(N + 255) / 256, 256>>>(N);
        dim3 grid((N + 63) / 64, MB / 64);
        gemm_popc_kernel<false><<<grid, 256>>>(actIn, wb + (size_t)l * 64000,
                                               sb + l * 512, aout, nullptr, N, K, KW);
        stats_kernel<<<MB / 128, 256>>>(aout, N);
        params_kernel<<<(N + 255) / 256, 256>>>(gam[l], bet[l], N);
        unsigned* actOut = (l % 2 == 0) ? act1 : act0;
        int KWn = LKW[l + 1];
        int nwarps = MB * KWn;
        pack_act_kernel<<<(nwarps + 7) / 8, 256>>>(aout, actOut, N, KWn);
        actIn = actOut;
    }
    // final classifier -> fp32 output (exact integers)
    {
        const int N = LN[5], K = LK[5], KW = LKW[5];
        dim3 grid((N + 63) / 64, MB / 64);
        gemm_popc_kernel<true><<<grid, 256>>>(actIn, wb + (size_t)5 * 64000,
                                              sb + 5 * 512, nullptr, (float*)d_out, N, K, KW);
    }
}

// round 5
// speedup vs baseline: 1.0076x; 1.0076x over previous
#include <cuda_runtime.h>
#include <cstdint>
#include <cstddef>

// Binarized 6-layer MLP, exact integer formulation.
//   dot(sign(a), sign(w)) = K - 2*popc(xor(bits_a, bits_w))   (bit = 1 iff value < 0)
//   BatchNorm sign computed exactly in double (mean = int_sum / 2^14 is exact).

#define MB 16384

// ---------------- static device scratch ----------------
__device__ __align__(16) unsigned g_act0[MB * 128];        // 8 MB
__device__ __align__(16) unsigned g_act1[MB * 16];         // 1 MB
__device__ __align__(16) unsigned g_wb[6][64000];
__device__ int                    g_sb[6][512];
__device__ short                  g_aout[(size_t)MB * 512];
__device__ int                    g_sum[512];
__device__ unsigned long long     g_sum2[512];
__device__ double                 g_mean[512];
__device__ double                 g_scale[512];
__device__ double                 g_shift[512];

// ---------------- pack float sign bits: bit = (v < 0) ----------------
__global__ void pack_sign_kernel(const float* __restrict__ src, unsigned* __restrict__ dst,
                                 int R, int C, int KW) {
    int warp = (int)((blockIdx.x * blockDim.x + threadIdx.x) >> 5);
    int lane = threadIdx.x & 31;
    if (warp >= R * KW) return;
    int row = warp / KW;
    int word = warp - row * KW;
    int col = word * 32 + lane;
    float v = (col < C) ? src[(size_t)row * C + col] : 0.0f;
    unsigned mask = __ballot_sync(0xffffffffu, v < 0.0f);
    if (lane == 0) dst[(size_t)row * KW + word] = mask;
}

__global__ void pack_b_kernel(const float* __restrict__ b, int* __restrict__ sb, int N) {
    int j = blockIdx.x * blockDim.x + threadIdx.x;
    if (j < N) sb[j] = (b[j] < 0.0f) ? -1 : 1;
}

__global__ void zero_stats_kernel(int N) {
    int j = blockIdx.x * blockDim.x + threadIdx.x;
    if (j < N) { g_sum[j] = 0; g_sum2[j] = 0ull; }
}

// ---------------- specialized layer-1 GEMM: M=16384, N=500, KW=128 ----------------
// 128x128 block tile, 256 threads, 8x8 per thread, double-buffered smem,
// both tiles transposed [word][row]. PAD=132 so every LDS.128 address
// ((w*132 + g*8)*4 bytes) is 16-byte aligned (132*4=528 = 33*16).
#define L1KW 128
#define L1N  500
#define PAD  132

__global__ void __launch_bounds__(256, 2)
gemm1_kernel(const unsigned* __restrict__ A, const unsigned* __restrict__ B,
             const int* __restrict__ sb, short* __restrict__ out) {
    __shared__ unsigned As[2][16][PAD];
    __shared__ unsigned Bs[2][16][PAD];

    const int tid = threadIdx.x;
    const int tx = tid & 15;          // col group
    const int ty = tid >> 4;          // row group
    const int row0 = blockIdx.y * 128;
    const int col0 = blockIdx.x * 128;

    int acc[8][8];
#pragma unroll
    for (int i = 0; i < 8; i++)
#pragma unroll
        for (int j = 0; j < 8; j++) acc[i][j] = 0;

    // transpose fill: 512 uint4 loads per tile, 2 per thread
    const int r_a0 = (tid + 0)   >> 2, wq_a0 = (tid + 0)   & 3;
    const int r_a1 = (tid + 256) >> 2, wq_a1 = (tid + 256) & 3;

    uint4 pa0, pa1, pb0, pb1;
    // prologue: chunk 0
    {
        pa0 = *(const uint4*)(A + (size_t)(row0 + r_a0) * L1KW + wq_a0 * 4);
        pa1 = *(const uint4*)(A + (size_t)(row0 + r_a1) * L1KW + wq_a1 * 4);
        int c0 = col0 + r_a0, c1 = col0 + r_a1;
        pb0 = (c0 < L1N) ? *(const uint4*)(B + (size_t)c0 * L1KW + wq_a0 * 4)
                         : make_uint4(0, 0, 0, 0);
        pb1 = (c1 < L1N) ? *(const uint4*)(B + (size_t)c1 * L1KW + wq_a1 * 4)
                         : make_uint4(0, 0, 0, 0);
        As[0][wq_a0 * 4 + 0][r_a0] = pa0.x; As[0][wq_a0 * 4 + 1][r_a0] = pa0.y;
        As[0][wq_a0 * 4 + 2][r_a0] = pa0.z; As[0][wq_a0 * 4 + 3][r_a0] = pa0.w;
        As[0][wq_a1 * 4 + 0][r_a1] = pa1.x; As[0][wq_a1 * 4 + 1][r_a1] = pa1.y;
        As[0][wq_a1 * 4 + 2][r_a1] = pa1.z; As[0][wq_a1 * 4 + 3][r_a1] = pa1.w;
        Bs[0][wq_a0 * 4 + 0][r_a0] = pb0.x; Bs[0][wq_a0 * 4 + 1][r_a0] = pb0.y;
        Bs[0][wq_a0 * 4 + 2][r_a0] = pb0.z; Bs[0][wq_a0 * 4 + 3][r_a0] = pb0.w;
        Bs[0][wq_a1 * 4 + 0][r_a1] = pb1.x; Bs[0][wq_a1 * 4 + 1][r_a1] = pb1.y;
        Bs[0][wq_a1 * 4 + 2][r_a1] = pb1.z; Bs[0][wq_a1 * 4 + 3][r_a1] = pb1.w;
    }
    __syncthreads();

#pragma unroll 1
    for (int ch = 0; ch < 8; ch++) {
        const int buf = ch & 1;
        if (ch < 7) {
            const int w0 = (ch + 1) * 16;
            pa0 = *(const uint4*)(A + (size_t)(row0 + r_a0) * L1KW + w0 + wq_a0 * 4);
            pa1 = *(const uint4*)(A + (size_t)(row0 + r_a1) * L1KW + w0 + wq_a1 * 4);
            int c0 = col0 + r_a0, c1 = col0 + r_a1;
            pb0 = (c0 < L1N) ? *(const uint4*)(B + (size_t)c0 * L1KW + w0 + wq_a0 * 4)
                             : make_uint4(0, 0, 0, 0);
            pb1 = (c1 < L1N) ? *(const uint4*)(B + (size_t)c1 * L1KW + w0 + wq_a1 * 4)
                             : make_uint4(0, 0, 0, 0);
        }
#pragma unroll
        for (int w = 0; w < 16; w++) {
            uint4 av0 = *(const uint4*)&As[buf][w][ty * 8];
            uint4 av1 = *(const uint4*)&As[buf][w][ty * 8 + 4];
            uint4 bv0 = *(const uint4*)&Bs[buf][w][tx * 8];
            uint4 bv1 = *(const uint4*)&Bs[buf][w][tx * 8 + 4];
            unsigned a[8] = {av0.x, av0.y, av0.z, av0.w, av1.x, av1.y, av1.z, av1.w};
            unsigned b[8] = {bv0.x, bv0.y, bv0.z, bv0.w, bv1.x, bv1.y, bv1.z, bv1.w};
#pragma unroll
            for (int i = 0; i < 8; i++)
#pragma unroll
                for (int j = 0; j < 8; j++)
                    acc[i][j] += __popc(a[i] ^ b[j]);
        }
        if (ch < 7) {
            const int nb = buf ^ 1;
            As[nb][wq_a0 * 4 + 0][r_a0] = pa0.x; As[nb][wq_a0 * 4 + 1][r_a0] = pa0.y;
            As[nb][wq_a0 * 4 + 2][r_a0] = pa0.z; As[nb][wq_a0 * 4 + 3][r_a0] = pa0.w;
            As[nb][wq_a1 * 4 + 0][r_a1] = pa1.x; As[nb][wq_a1 * 4 + 1][r_a1] = pa1.y;
            As[nb][wq_a1 * 4 + 2][r_a1] = pa1.z; As[nb][wq_a1 * 4 + 3][r_a1] = pa1.w;
            Bs[nb][wq_a0 * 4 + 0][r_a0] = pb0.x; Bs[nb][wq_a0 * 4 + 1][r_a0] = pb0.y;
            Bs[nb][wq_a0 * 4 + 2][r_a0] = pb0.z; Bs[nb][wq_a0 * 4 + 3][r_a0] = pb0.w;
            Bs[nb][wq_a1 * 4 + 0][r_a1] = pb1.x; Bs[nb][wq_a1 * 4 + 1][r_a1] = pb1.y;
            Bs[nb][wq_a1 * 4 + 2][r_a1] = pb1.z; Bs[nb][wq_a1 * 4 + 3][r_a1] = pb1.w;
        }
        __syncthreads();
    }

    // epilogue: v = K - 2*popc + sb[col]
    int sbr[8];
#pragma unroll
    for (int j = 0; j < 8; j++) {
        int col = col0 + tx * 8 + j;
        sbr[j] = (col < L1N) ? sb[col] : 0;
    }
#pragma unroll
    for (int i = 0; i < 8; i++) {
        int row = row0 + ty * 8 + i;
#pragma unroll
        for (int j = 0; j < 8; j++) {
            int col = col0 + tx * 8 + j;
            if (col < L1N)
                out[(size_t)row * L1N + col] = (short)(4096 - 2 * acc[i][j] + sbr[j]);
        }
    }
}

// ---------------- generic xor-popcount GEMM (small layers): 64x64, 4x4/thread ----------------
template <bool FINAL>
__global__ void __launch_bounds__(256)
gemm_popc_kernel(const unsigned* __restrict__ abits, const unsigned* __restrict__ bbits,
                 const int* __restrict__ sb, short* __restrict__ aout,
                 float* __restrict__ fout, int N, int K, int KW) {
    __shared__ unsigned As[64][17];
    __shared__ unsigned Bs[16][64];

    const int tx = threadIdx.x & 15;
    const int ty = threadIdx.x >> 4;
    const int row0 = blockIdx.y * 64;
    const int col0 = blockIdx.x * 64;

    int acc[4][4];
#pragma unroll
    for (int i = 0; i < 4; i++)
#pragma unroll
        for (int j = 0; j < 4; j++) acc[i][j] = 0;

    const int nchunks = (KW + 15) >> 4;
    for (int ch = 0; ch < nchunks; ch++) {
        const int w0 = ch * 16;
        for (int idx = threadIdx.x; idx < 64 * 16; idx += 256) {
            int r = idx >> 4, w = idx & 15;
            unsigned v = 0;
            if (w0 + w < KW) v = abits[(size_t)(row0 + r) * KW + w0 + w];
            As[r][w] = v;
        }
        for (int idx = threadIdx.x; idx < 64 * 16; idx += 256) {
            int c = idx & 63, w = idx >> 6;
            unsigned v = 0;
            int col = col0 + c;
            if (col < N && w0 + w < KW) v = bbits[(size_t)col * KW + w0 + w];
            Bs[w][c] = v;
        }
        __syncthreads();
#pragma unroll
        for (int w = 0; w < 16; w++) {
            unsigned a0 = As[ty * 4 + 0][w];
            unsigned a1 = As[ty * 4 + 1][w];
            unsigned a2 = As[ty * 4 + 2][w];
            unsigned a3 = As[ty * 4 + 3][w];
            uint4 bv = *(const uint4*)&Bs[w][tx * 4];
            acc[0][0] += __popc(a0 ^ bv.x); acc[0][1] += __popc(a0 ^ bv.y);
            acc[0][2] += __popc(a0 ^ bv.z); acc[0][3] += __popc(a0 ^ bv.w);
            acc[1][0] += __popc(a1 ^ bv.x); acc[1][1] += __popc(a1 ^ bv.y);
            acc[1][2] += __popc(a1 ^ bv.z); acc[1][3] += __popc(a1 ^ bv.w);
            acc[2][0] += __popc(a2 ^ bv.x); acc[2][1] += __popc(a2 ^ bv.y);
            acc[2][2] += __popc(a2 ^ bv.z); acc[2][3] += __popc(a2 ^ bv.w);
            acc[3][0] += __popc(a3 ^ bv.x); acc[3][1] += __popc(a3 ^ bv.y);
            acc[3][2] += __popc(a3 ^ bv.z); acc[3][3] += __popc(a3 ^ bv.w);
        }
        __syncthreads();
    }

#pragma unroll
    for (int i = 0; i < 4; i++) {
        int row = row0 + ty * 4 + i;
#pragma unroll
        for (int j = 0; j < 4; j++) {
            int col = col0 + tx * 4 + j;
            if (col < N) {
                int v = K - 2 * acc[i][j] + sb[col];
                if (FINAL) fout[(size_t)row * N + col] = (float)v;
                else       aout[(size_t)row * N + col] = (short)v;
            }
        }
    }
}

// ---------------- per-column sums ----------------
__global__ void stats_kernel(const short* __restrict__ a, int N) {
    const int r0 = blockIdx.x * 64;
    for (int c = threadIdx.x; c < N; c += 256) {
        int s = 0;
        long long s2 = 0;
        for (int r = 0; r < 64; r++) {
            int v = a[(size_t)(r0 + r) * N + c];
            s += v;
            s2 += (long long)(v * v);
        }
        atomicAdd(&g_sum[c], s);
        atomicAdd(&g_sum2[c], (unsigned long long)s2);
    }
}

__global__ void params_kernel(const float* __restrict__ gam, const float* __restrict__ bet, int N) {
    int j = blockIdx.x * blockDim.x + threadIdx.x;
    if (j >= N) return;
    double mean = (double)g_sum[j] / 16384.0;
    double var  = (double)(long long)g_sum2[j] / 16384.0 - mean * mean;
    double invstd = 1.0 / sqrt(var + 1e-5);
    g_mean[j]  = mean;
    g_scale[j] = invstd * (double)gam[j];
    g_shift[j] = (double)bet[j];
}

__global__ void pack_act_kernel(const short* __restrict__ a, unsigned* __restrict__ dst,
                                int C, int KW) {
    int warp = (int)((blockIdx.x * blockDim.x + threadIdx.x) >> 5);
    int lane = threadIdx.x & 31;
    if (warp >= MB * KW) return;
    int row = warp / KW;
    int word = warp - row * KW;
    int col = word * 32 + lane;
    bool neg = false;
    if (col < C) {
        double y = ((double)a[(size_t)row * C + col] - g_mean[col]) * g_scale[col] + g_shift[col];
        neg = (y < 0.0);
    }
    unsigned mask = __ballot_sync(0xffffffffu, neg);
    if (lane == 0) dst[(size_t)row * KW + word] = mask;
}

// ---------------- host orchestration ----------------
extern "C" void kernel_launch(void* const* d_in, const int* in_sizes, int n_in,
                              void* d_out, int out_size) {
    (void)in_sizes; (void)n_in; (void)out_size;
    static const int LK[6]  = {4096, 500, 400, 350, 300, 300};
    static const int LN[6]  = {500, 400, 350, 300, 300, 35};
    static const int LKW[6] = {128, 16, 13, 11, 10, 10};

    const float* x = (const float*)d_in[0];
    const float* W[6]; const float* bb[6]; const float* gam[5]; const float* bet[5];
    for (int l = 0; l < 5; l++) {
        W[l]   = (const float*)d_in[1 + 4 * l];
        bb[l]  = (const float*)d_in[2 + 4 * l];
        gam[l] = (const float*)d_in[3 + 4 * l];
        bet[l] = (const float*)d_in[4 + 4 * l];
    }
    W[5]  = (const float*)d_in[21];
    bb[5] = (const float*)d_in[22];

    unsigned *act0, *act1, *wb;
    int *sb;
    short *aout;
    cudaGetSymbolAddress((void**)&act0, g_act0);
    cudaGetSymbolAddress((void**)&act1, g_act1);
    cudaGetSymbolAddress((void**)&wb,   g_wb);
    cudaGetSymbolAddress((void**)&sb,   g_sb);
    cudaGetSymbolAddress((void**)&aout, g_aout);

    // Launch order arranged so the 6th launch is gemm1 (ncu -s 5 -c 1 captures it).
    pack_sign_kernel<<<(MB * 128 + 7) / 8, 256>>>(x, act0, MB, 4096, 128);
    pack_sign_kernel<<<(LN[0] * LKW[0] + 7) / 8, 256>>>(W[0], wb, LN[0], LK[0], LKW[0]);
    pack_b_kernel<<<(LN[0] + 255) / 256, 256>>>(bb[0], sb, LN[0]);
    zero_stats_kernel<<<(LN[0] + 255) / 256, 256>>>(LN[0]);
    pack_sign_kernel<<<(LN[1] * LKW[1] + 7) / 8, 256>>>(W[1], wb + 64000, LN[1], LK[1], LKW[1]);
    // (6) layer-1 GEMM (specialized)
    {
        dim3 grid(4, MB / 128);
        gemm1_kernel<<<grid, 256>>>(act0, wb, sb, aout);
    }
    pack_b_kernel<<<(LN[1] + 255) / 256, 256>>>(bb[1], sb + 512, LN[1]);
    for (int l = 2; l < 6; l++) {
        pack_sign_kernel<<<(LN[l] * LKW[l] + 7) / 8, 256>>>(W[l], wb + (size_t)l * 64000,
                                                            LN[l], LK[l], LKW[l]);
        pack_b_kernel<<<(LN[l] + 255) / 256, 256>>>(bb[l], sb + l * 512, LN[l]);
    }
    stats_kernel<<<MB / 64, 256>>>(aout, LN[0]);
    params_kernel<<<(LN[0] + 255) / 256, 256>>>(gam[0], bet[0], LN[0]);
    pack_act_kernel<<<(MB * LKW[1] + 7) / 8, 256>>>(aout, act1, LN[0], LKW[1]);

    unsigned* actIn = act1;
    for (int l = 1; l < 5; l++) {
        const int N = LN[l], K = LK[l], KW = LKW[l];
        zero_stats_kernel<<<(N + 255) / 256, 256>>>(N);
        dim3 grid((N + 63) / 64, MB / 64);
        gemm_popc_kernel<false><<<grid, 256>>>(actIn, wb + (size_t)l * 64000,
                                               sb + l * 512, aout, nullptr, N, K, KW);
        stats_kernel<<<MB / 64, 256>>>(aout, N);
        params_kernel<<<(N + 255) / 256, 256>>>(gam[l], bet[l], N);
        unsigned* actOut = (l % 2 == 0) ? act1 : act0;
        int KWn = LKW[l + 1];
        pack_act_kernel<<<(MB * KWn + 7) / 8, 256>>>(aout, actOut, N, KWn);
        actIn = actOut;
    }
    // final classifier -> fp32 output (exact integers)
    {
        const int N = LN[5], K = LK[5], KW = LKW[5];
        dim3 grid((N + 63) / 64, MB / 64);
        gemm_popc_kernel<true><<<grid, 256>>>(actIn, wb + (size_t)5 * 64000,
                                              sb + 5 * 512, nullptr, (float*)d_out, N, K, KW);
    }
}

// round 6
// speedup vs baseline: 1.2094x; 1.2002x over previous
#include <cuda_runtime.h>
#include <cstdint>
#include <cstddef>

// Binarized 6-layer MLP, exact integer formulation.
//   dot(sign(a), sign(w)) = K - 2*popc(xor(bits_a, bits_w))   (bit = 1 iff value < 0)
//   BN+Hardtanh+binarize folds to ONE integer threshold compare per column
//   (thresholds computed once per layer in double; zero per-element FP64).

#define MB 16384

// ---------------- static device scratch ----------------
__device__ __align__(16) unsigned g_act0[MB * 128];        // 8 MB
__device__ __align__(16) unsigned g_act1[MB * 16];         // 1 MB
__device__ __align__(16) unsigned g_wb[6][64000];
__device__ int                    g_sb[6][512];
__device__ short                  g_aout[(size_t)MB * 512];
__device__ int                    g_sum[512];
__device__ unsigned long long     g_sum2[512];
__device__ int                    g_thr[512];    // integer threshold
__device__ int                    g_mode[512];   // 0: neg = (a < thr), 1: neg = (a > thr)

// ---------------- pack float sign bits: bit = (v < 0) ----------------
__global__ void pack_sign_kernel(const float* __restrict__ src, unsigned* __restrict__ dst,
                                 int R, int C, int KW) {
    int warp = (int)((blockIdx.x * blockDim.x + threadIdx.x) >> 5);
    int lane = threadIdx.x & 31;
    if (warp >= R * KW) return;
    int row = warp / KW;
    int word = warp - row * KW;
    int col = word * 32 + lane;
    float v = (col < C) ? src[(size_t)row * C + col] : 0.0f;
    unsigned mask = __ballot_sync(0xffffffffu, v < 0.0f);
    if (lane == 0) dst[(size_t)row * KW + word] = mask;
}

__global__ void pack_b_kernel(const float* __restrict__ b, int* __restrict__ sb, int N) {
    int j = blockIdx.x * blockDim.x + threadIdx.x;
    if (j < N) sb[j] = (b[j] < 0.0f) ? -1 : 1;
}

__global__ void zero_stats_kernel(int N) {
    int j = blockIdx.x * blockDim.x + threadIdx.x;
    if (j < N) { g_sum[j] = 0; g_sum2[j] = 0ull; }
}

// ---------------- specialized layer-1 GEMM: M=16384, N=500, KW=128 ----------------
#define L1KW 128
#define L1N  500
#define PAD  132   // 132*4=528 bytes, multiple of 16 -> LDS.128 aligned

__global__ void __launch_bounds__(256, 2)
gemm1_kernel(const unsigned* __restrict__ A, const unsigned* __restrict__ B,
             const int* __restrict__ sb, short* __restrict__ out) {
    __shared__ unsigned As[2][16][PAD];
    __shared__ unsigned Bs[2][16][PAD];

    const int tid = threadIdx.x;
    const int tx = tid & 15;
    const int ty = tid >> 4;
    const int row0 = blockIdx.y * 128;
    const int col0 = blockIdx.x * 128;

    int acc[8][8];
#pragma unroll
    for (int i = 0; i < 8; i++)
#pragma unroll
        for (int j = 0; j < 8; j++) acc[i][j] = 0;

    const int r_a0 = (tid + 0)   >> 2, wq_a0 = (tid + 0)   & 3;
    const int r_a1 = (tid + 256) >> 2, wq_a1 = (tid + 256) & 3;

    uint4 pa0, pa1, pb0, pb1;
    {
        pa0 = *(const uint4*)(A + (size_t)(row0 + r_a0) * L1KW + wq_a0 * 4);
        pa1 = *(const uint4*)(A + (size_t)(row0 + r_a1) * L1KW + wq_a1 * 4);
        int c0 = col0 + r_a0, c1 = col0 + r_a1;
        pb0 = (c0 < L1N) ? *(const uint4*)(B + (size_t)c0 * L1KW + wq_a0 * 4)
                         : make_uint4(0, 0, 0, 0);
        pb1 = (c1 < L1N) ? *(const uint4*)(B + (size_t)c1 * L1KW + wq_a1 * 4)
                         : make_uint4(0, 0, 0, 0);
        As[0][wq_a0 * 4 + 0][r_a0] = pa0.x; As[0][wq_a0 * 4 + 1][r_a0] = pa0.y;
        As[0][wq_a0 * 4 + 2][r_a0] = pa0.z; As[0][wq_a0 * 4 + 3][r_a0] = pa0.w;
        As[0][wq_a1 * 4 + 0][r_a1] = pa1.x; As[0][wq_a1 * 4 + 1][r_a1] = pa1.y;
        As[0][wq_a1 * 4 + 2][r_a1] = pa1.z; As[0][wq_a1 * 4 + 3][r_a1] = pa1.w;
        Bs[0][wq_a0 * 4 + 0][r_a0] = pb0.x; Bs[0][wq_a0 * 4 + 1][r_a0] = pb0.y;
        Bs[0][wq_a0 * 4 + 2][r_a0] = pb0.z; Bs[0][wq_a0 * 4 + 3][r_a0] = pb0.w;
        Bs[0][wq_a1 * 4 + 0][r_a1] = pb1.x; Bs[0][wq_a1 * 4 + 1][r_a1] = pb1.y;
        Bs[0][wq_a1 * 4 + 2][r_a1] = pb1.z; Bs[0][wq_a1 * 4 + 3][r_a1] = pb1.w;
    }
    __syncthreads();

#pragma unroll 1
    for (int ch = 0; ch < 8; ch++) {
        const int buf = ch & 1;
        if (ch < 7) {
            const int w0 = (ch + 1) * 16;
            pa0 = *(const uint4*)(A + (size_t)(row0 + r_a0) * L1KW + w0 + wq_a0 * 4);
            pa1 = *(const uint4*)(A + (size_t)(row0 + r_a1) * L1KW + w0 + wq_a1 * 4);
            int c0 = col0 + r_a0, c1 = col0 + r_a1;
            pb0 = (c0 < L1N) ? *(const uint4*)(B + (size_t)c0 * L1KW + w0 + wq_a0 * 4)
                             : make_uint4(0, 0, 0, 0);
            pb1 = (c1 < L1N) ? *(const uint4*)(B + (size_t)c1 * L1KW + w0 + wq_a1 * 4)
                             : make_uint4(0, 0, 0, 0);
        }
#pragma unroll
        for (int w = 0; w < 16; w++) {
            uint4 av0 = *(const uint4*)&As[buf][w][ty * 8];
            uint4 av1 = *(const uint4*)&As[buf][w][ty * 8 + 4];
            uint4 bv0 = *(const uint4*)&Bs[buf][w][tx * 8];
            uint4 bv1 = *(const uint4*)&Bs[buf][w][tx * 8 + 4];
            unsigned a[8] = {av0.x, av0.y, av0.z, av0.w, av1.x, av1.y, av1.z, av1.w};
            unsigned b[8] = {bv0.x, bv0.y, bv0.z, bv0.w, bv1.x, bv1.y, bv1.z, bv1.w};
#pragma unroll
            for (int i = 0; i < 8; i++)
#pragma unroll
                for (int j = 0; j < 8; j++)
                    acc[i][j] += __popc(a[i] ^ b[j]);
        }
        if (ch < 7) {
            const int nb = buf ^ 1;
            As[nb][wq_a0 * 4 + 0][r_a0] = pa0.x; As[nb][wq_a0 * 4 + 1][r_a0] = pa0.y;
            As[nb][wq_a0 * 4 + 2][r_a0] = pa0.z; As[nb][wq_a0 * 4 + 3][r_a0] = pa0.w;
            As[nb][wq_a1 * 4 + 0][r_a1] = pa1.x; As[nb][wq_a1 * 4 + 1][r_a1] = pa1.y;
            As[nb][wq_a1 * 4 + 2][r_a1] = pa1.z; As[nb][wq_a1 * 4 + 3][r_a1] = pa1.w;
            Bs[nb][wq_a0 * 4 + 0][r_a0] = pb0.x; Bs[nb][wq_a0 * 4 + 1][r_a0] = pb0.y;
            Bs[nb][wq_a0 * 4 + 2][r_a0] = pb0.z; Bs[nb][wq_a0 * 4 + 3][r_a0] = pb0.w;
            Bs[nb][wq_a1 * 4 + 0][r_a1] = pb1.x; Bs[nb][wq_a1 * 4 + 1][r_a1] = pb1.y;
            Bs[nb][wq_a1 * 4 + 2][r_a1] = pb1.z; Bs[nb][wq_a1 * 4 + 3][r_a1] = pb1.w;
        }
        __syncthreads();
    }

    int sbr[8];
#pragma unroll
    for (int j = 0; j < 8; j++) {
        int col = col0 + tx * 8 + j;
        sbr[j] = (col < L1N) ? sb[col] : 0;
    }
#pragma unroll
    for (int i = 0; i < 8; i++) {
        int row = row0 + ty * 8 + i;
#pragma unroll
        for (int j = 0; j < 8; j++) {
            int col = col0 + tx * 8 + j;
            if (col < L1N)
                out[(size_t)row * L1N + col] = (short)(4096 - 2 * acc[i][j] + sbr[j]);
        }
    }
}

// ---------------- generic xor-popcount GEMM (small layers) ----------------
template <bool FINAL>
__global__ void __launch_bounds__(256)
gemm_popc_kernel(const unsigned* __restrict__ abits, const unsigned* __restrict__ bbits,
                 const int* __restrict__ sb, short* __restrict__ aout,
                 float* __restrict__ fout, int N, int K, int KW) {
    __shared__ unsigned As[64][17];
    __shared__ unsigned Bs[16][64];

    const int tx = threadIdx.x & 15;
    const int ty = threadIdx.x >> 4;
    const int row0 = blockIdx.y * 64;
    const int col0 = blockIdx.x * 64;

    int acc[4][4];
#pragma unroll
    for (int i = 0; i < 4; i++)
#pragma unroll
        for (int j = 0; j < 4; j++) acc[i][j] = 0;

    const int nchunks = (KW + 15) >> 4;
    for (int ch = 0; ch < nchunks; ch++) {
        const int w0 = ch * 16;
        for (int idx = threadIdx.x; idx < 64 * 16; idx += 256) {
            int r = idx >> 4, w = idx & 15;
            unsigned v = 0;
            if (w0 + w < KW) v = abits[(size_t)(row0 + r) * KW + w0 + w];
            As[r][w] = v;
        }
        for (int idx = threadIdx.x; idx < 64 * 16; idx += 256) {
            int c = idx & 63, w = idx >> 6;
            unsigned v = 0;
            int col = col0 + c;
            if (col < N && w0 + w < KW) v = bbits[(size_t)col * KW + w0 + w];
            Bs[w][c] = v;
        }
        __syncthreads();
#pragma unroll
        for (int w = 0; w < 16; w++) {
            unsigned a0 = As[ty * 4 + 0][w];
            unsigned a1 = As[ty * 4 + 1][w];
            unsigned a2 = As[ty * 4 + 2][w];
            unsigned a3 = As[ty * 4 + 3][w];
            uint4 bv = *(const uint4*)&Bs[w][tx * 4];
            acc[0][0] += __popc(a0 ^ bv.x); acc[0][1] += __popc(a0 ^ bv.y);
            acc[0][2] += __popc(a0 ^ bv.z); acc[0][3] += __popc(a0 ^ bv.w);
            acc[1][0] += __popc(a1 ^ bv.x); acc[1][1] += __popc(a1 ^ bv.y);
            acc[1][2] += __popc(a1 ^ bv.z); acc[1][3] += __popc(a1 ^ bv.w);
            acc[2][0] += __popc(a2 ^ bv.x); acc[2][1] += __popc(a2 ^ bv.y);
            acc[2][2] += __popc(a2 ^ bv.z); acc[2][3] += __popc(a2 ^ bv.w);
            acc[3][0] += __popc(a3 ^ bv.x); acc[3][1] += __popc(a3 ^ bv.y);
            acc[3][2] += __popc(a3 ^ bv.z); acc[3][3] += __popc(a3 ^ bv.w);
        }
        __syncthreads();
    }

#pragma unroll
    for (int i = 0; i < 4; i++) {
        int row = row0 + ty * 4 + i;
#pragma unroll
        for (int j = 0; j < 4; j++) {
            int col = col0 + tx * 4 + j;
            if (col < N) {
                int v = K - 2 * acc[i][j] + sb[col];
                if (FINAL) fout[(size_t)row * N + col] = (float)v;
                else       aout[(size_t)row * N + col] = (short)v;
            }
        }
    }
}

// ---------------- per-column sums ----------------
__global__ void stats_kernel(const short* __restrict__ a, int N) {
    const int r0 = blockIdx.x * 64;
    for (int c = threadIdx.x; c < N; c += 256) {
        int s = 0;
        long long s2 = 0;
        for (int r = 0; r < 64; r++) {
            int v = a[(size_t)(r0 + r) * N + c];
            s += v;
            s2 += (long long)(v * v);
        }
        atomicAdd(&g_sum[c], s);
        atomicAdd(&g_sum2[c], (unsigned long long)s2);
    }
}

// thresholds: O(N) doubles, once per layer — negligible FP64.
// y = (a - mean)*scale + shift ; scale = invstd*gamma
//   scale > 0: neg ⟺ a < ceil(mean - shift/scale)
//   scale < 0: neg ⟺ a > floor(mean - shift/scale)
//   scale = 0: neg ⟺ shift < 0 (constant)
__global__ void params_kernel(const float* __restrict__ gam, const float* __restrict__ bet, int N) {
    int j = blockIdx.x * blockDim.x + threadIdx.x;
    if (j >= N) return;
    double mean = (double)g_sum[j] / 16384.0;
    double var  = (double)(long long)g_sum2[j] / 16384.0 - mean * mean;
    double invstd = 1.0 / sqrt(var + 1e-5);
    double scale = invstd * (double)gam[j];
    double shift = (double)bet[j];
    int thr, mode;
    if (scale > 0.0) {
        double t = mean - shift / scale;
        t = fmin(fmax(t, -1.0e9), 1.0e9);
        thr = (int)ceil(t);  mode = 0;            // neg = a < thr
    } else if (scale < 0.0) {
        double t = mean - shift / scale;
        t = fmin(fmax(t, -1.0e9), 1.0e9);
        thr = (int)floor(t); mode = 1;            // neg = a > thr
    } else {
        mode = 0;
        thr = (shift < 0.0) ? 2147483647 : (-2147483647 - 1);  // always / never
    }
    g_thr[j] = thr;
    g_mode[j] = mode;
}

// ---------------- pack next-layer sign bits: pure integer compare ----------------
__global__ void pack_act_kernel(const short* __restrict__ a, unsigned* __restrict__ dst,
                                int C, int KW) {
    int warp = (int)((blockIdx.x * blockDim.x + threadIdx.x) >> 5);
    int lane = threadIdx.x & 31;
    if (warp >= MB * KW) return;
    int row = warp / KW;
    int word = warp - row * KW;
    int col = word * 32 + lane;
    bool neg = false;
    if (col < C) {
        int v = a[(size_t)row * C + col];
        int thr = g_thr[col];
        neg = g_mode[col] ? (v > thr) : (v < thr);
    }
    unsigned mask = __ballot_sync(0xffffffffu, neg);
    if (lane == 0) dst[(size_t)row * KW + word] = mask;
}

// ---------------- host orchestration ----------------
extern "C" void kernel_launch(void* const* d_in, const int* in_sizes, int n_in,
                              void* d_out, int out_size) {
    (void)in_sizes; (void)n_in; (void)out_size;
    static const int LK[6]  = {4096, 500, 400, 350, 300, 300};
    static const int LN[6]  = {500, 400, 350, 300, 300, 35};
    static const int LKW[6] = {128, 16, 13, 11, 10, 10};

    const float* x = (const float*)d_in[0];
    const float* W[6]; const float* bb[6]; const float* gam[5]; const float* bet[5];
    for (int l = 0; l < 5; l++) {
        W[l]   = (const float*)d_in[1 + 4 * l];
        bb[l]  = (const float*)d_in[2 + 4 * l];
        gam[l] = (const float*)d_in[3 + 4 * l];
        bet[l] = (const float*)d_in[4 + 4 * l];
    }
    W[5]  = (const float*)d_in[21];
    bb[5] = (const float*)d_in[22];

    unsigned *act0, *act1, *wb;
    int *sb;
    short *aout;
    cudaGetSymbolAddress((void**)&act0, g_act0);
    cudaGetSymbolAddress((void**)&act1, g_act1);
    cudaGetSymbolAddress((void**)&wb,   g_wb);
    cudaGetSymbolAddress((void**)&sb,   g_sb);
    cudaGetSymbolAddress((void**)&aout, g_aout);

    // Launch order: gemm1 is the 4th launch (observed ncu capture position).
    pack_sign_kernel<<<(MB * 128 + 7) / 8, 256>>>(x, act0, MB, 4096, 128);          // 1
    pack_sign_kernel<<<(LN[0] * LKW[0] + 7) / 8, 256>>>(W[0], wb, LN[0], LK[0], LKW[0]); // 2
    pack_b_kernel<<<(LN[0] + 255) / 256, 256>>>(bb[0], sb, LN[0]);                  // 3
    {                                                                               // 4: gemm1
        dim3 grid(4, MB / 128);
        gemm1_kernel<<<grid, 256>>>(act0, wb, sb, aout);
    }
    zero_stats_kernel<<<(LN[0] + 255) / 256, 256>>>(LN[0]);
    for (int l = 1; l < 6; l++) {
        pack_sign_kernel<<<(LN[l] * LKW[l] + 7) / 8, 256>>>(W[l], wb + (size_t)l * 64000,
                                                            LN[l], LK[l], LKW[l]);
        pack_b_kernel<<<(LN[l] + 255) / 256, 256>>>(bb[l], sb + l * 512, LN[l]);
    }
    stats_kernel<<<MB / 64, 256>>>(aout, LN[0]);
    params_kernel<<<(LN[0] + 255) / 256, 256>>>(gam[0], bet[0], LN[0]);
    pack_act_kernel<<<(MB * LKW[1] + 7) / 8, 256>>>(aout, act1, LN[0], LKW[1]);

    unsigned* actIn = act1;
    for (int l = 1; l < 5; l++) {
        const int N = LN[l], K = LK[l], KW = LKW[l];
        zero_stats_kernel<<<(N + 255) / 256, 256>>>(N);
        dim3 grid((N + 63) / 64, MB / 64);
        gemm_popc_kernel<false><<<grid, 256>>>(actIn, wb + (size_t)l * 64000,
                                               sb + l * 512, aout, nullptr, N, K, KW);
        stats_kernel<<<MB / 64, 256>>>(aout, N);
        params_kernel<<<(N + 255) / 256, 256>>>(gam[l], bet[l], N);
        unsigned* actOut = (l % 2 == 0) ? act1 : act0;
        int KWn = LKW[l + 1];
        pack_act_kernel<<<(MB * KWn + 7) / 8, 256>>>(aout, actOut, N, KWn);
        actIn = actOut;
    }
    // final classifier -> fp32 output (exact integers)
    {
        const int N = LN[5], K = LK[5], KW = LKW[5];
        dim3 grid((N + 63) / 64, MB / 64);
        gemm_popc_kernel<true><<<grid, 256>>>(actIn, wb + (size_t)5 * 64000,
                                              sb + 5 * 512, nullptr, (float*)d_out, N, K, KW);
    }
}

// round 7
// speedup vs baseline: 1.3283x; 1.0983x over previous
#include <cuda_runtime.h>
#include <cstdint>
#include <cstddef>

// Binarized 6-layer MLP, exact integer formulation.
//   dot(sign(a), sign(w)) = K - 2*popc(xor(bits_a, bits_w))
//   BN+Hardtanh+binarize folds to ONE integer threshold compare per column.
// This round: IMAD-pipe accumulation (opaque `one`), occupancy-tuned gemm1,
// stats fused into GEMM epilogues, zero/stats launches eliminated.

#define MB 16384

// ---------------- static device scratch ----------------
__device__ __align__(16) unsigned g_act0[MB * 128];        // 8 MB
__device__ __align__(16) unsigned g_act1[MB * 16];         // 1 MB
__device__ __align__(16) unsigned g_wb[6][64000];
__device__ int                    g_sb[6][512];
__device__ short                  g_aout[(size_t)MB * 512];
__device__ int                    g_sum[512];
__device__ unsigned long long     g_sum2[512];
__device__ int                    g_thr[512];    // integer threshold
__device__ int                    g_mode[512];   // 0: neg = (a < thr), 1: neg = (a > thr)

// ---------------- pack float sign bits: bit = (v < 0) ----------------
__global__ void pack_sign_kernel(const float* __restrict__ src, unsigned* __restrict__ dst,
                                 int R, int C, int KW) {
    int warp = (int)((blockIdx.x * blockDim.x + threadIdx.x) >> 5);
    int lane = threadIdx.x & 31;
    if (warp >= R * KW) return;
    int row = warp / KW;
    int word = warp - row * KW;
    int col = word * 32 + lane;
    float v = (col < C) ? src[(size_t)row * C + col] : 0.0f;
    unsigned mask = __ballot_sync(0xffffffffu, v < 0.0f);
    if (lane == 0) dst[(size_t)row * KW + word] = mask;
}

// pack bias sign; optionally zero the stats arrays (layer 1 only, pre-gemm1)
__global__ void pack_b_kernel(const float* __restrict__ b, int* __restrict__ sb, int N,
                              int zero_stats) {
    int j = blockIdx.x * blockDim.x + threadIdx.x;
    if (j < N) sb[j] = (b[j] < 0.0f) ? -1 : 1;
    if (zero_stats && j < 512) { g_sum[j] = 0; g_sum2[j] = 0ull; }
}

// ---------------- specialized layer-1 GEMM: M=16384, N=500(→512), KW=128 ----------------
// 128x64 CTA tile, 256 threads (16x16), 8x4 micro-tile, double-buffered smem,
// IMAD accumulation via opaque `one`, fused per-column stats (sum, sum^2).
#define L1KW 128
#define L1N  500
#define APAD 132   // 132*4=528, multiple of 16 -> LDS.128 aligned
#define BPAD 68    // 68*4=272, multiple of 16

__global__ void __launch_bounds__(256, 3)
gemm1_kernel(const unsigned* __restrict__ A, const unsigned* __restrict__ B,
             const int* __restrict__ sb, short* __restrict__ out, int one) {
    __shared__ unsigned As[2][16][APAD];   // [w][row 0..127]
    __shared__ unsigned Bs[2][16][BPAD];   // [w][col 0..63]

    const int tid = threadIdx.x;
    const int tx = tid & 15;          // col group: cols tx*4 .. +3
    const int ty = tid >> 4;          // row group: rows ty*8 .. +7
    const int row0 = blockIdx.y * 128;
    const int col0 = blockIdx.x * 64;

    int acc[8][4];
#pragma unroll
    for (int i = 0; i < 8; i++)
#pragma unroll
        for (int j = 0; j < 4; j++) acc[i][j] = 0;

    const int ra = tid >> 2;          // 0..63
    const int wq = tid & 3;           // uint4 index within 16 words

    uint4 pa0, pa1, pb;
    {   // prologue: chunk 0
        pa0 = *(const uint4*)(A + (size_t)(row0 + ra) * L1KW + wq * 4);
        pa1 = *(const uint4*)(A + (size_t)(row0 + ra + 64) * L1KW + wq * 4);
        int cb = col0 + ra;
        pb = (cb < L1N) ? *(const uint4*)(B + (size_t)cb * L1KW + wq * 4)
                        : make_uint4(0, 0, 0, 0);
        As[0][wq * 4 + 0][ra] = pa0.x; As[0][wq * 4 + 1][ra] = pa0.y;
        As[0][wq * 4 + 2][ra] = pa0.z; As[0][wq * 4 + 3][ra] = pa0.w;
        As[0][wq * 4 + 0][ra + 64] = pa1.x; As[0][wq * 4 + 1][ra + 64] = pa1.y;
        As[0][wq * 4 + 2][ra + 64] = pa1.z; As[0][wq * 4 + 3][ra + 64] = pa1.w;
        Bs[0][wq * 4 + 0][ra] = pb.x; Bs[0][wq * 4 + 1][ra] = pb.y;
        Bs[0][wq * 4 + 2][ra] = pb.z; Bs[0][wq * 4 + 3][ra] = pb.w;
    }
    __syncthreads();

#pragma unroll 1
    for (int ch = 0; ch < 8; ch++) {
        const int buf = ch & 1;
        if (ch < 7) {
            const int w0 = (ch + 1) * 16;
            pa0 = *(const uint4*)(A + (size_t)(row0 + ra) * L1KW + w0 + wq * 4);
            pa1 = *(const uint4*)(A + (size_t)(row0 + ra + 64) * L1KW + w0 + wq * 4);
            int cb = col0 + ra;
            pb = (cb < L1N) ? *(const uint4*)(B + (size_t)cb * L1KW + w0 + wq * 4)
                            : make_uint4(0, 0, 0, 0);
        }
#pragma unroll
        for (int w = 0; w < 16; w++) {
            uint4 av0 = *(const uint4*)&As[buf][w][ty * 8];
            uint4 av1 = *(const uint4*)&As[buf][w][ty * 8 + 4];
            uint4 bv  = *(const uint4*)&Bs[buf][w][tx * 4];
            unsigned a[8] = {av0.x, av0.y, av0.z, av0.w, av1.x, av1.y, av1.z, av1.w};
            unsigned b[4] = {bv.x, bv.y, bv.z, bv.w};
#pragma unroll
            for (int i = 0; i < 8; i++)
#pragma unroll
                for (int j = 0; j < 4; j++)
                    acc[i][j] += __popc(a[i] ^ b[j]) * one;   // IMAD -> fma pipe
        }
        if (ch < 7) {
            const int nb = buf ^ 1;
            As[nb][wq * 4 + 0][ra] = pa0.x; As[nb][wq * 4 + 1][ra] = pa0.y;
            As[nb][wq * 4 + 2][ra] = pa0.z; As[nb][wq * 4 + 3][ra] = pa0.w;
            As[nb][wq * 4 + 0][ra + 64] = pa1.x; As[nb][wq * 4 + 1][ra + 64] = pa1.y;
            As[nb][wq * 4 + 2][ra + 64] = pa1.z; As[nb][wq * 4 + 3][ra + 64] = pa1.w;
            Bs[nb][wq * 4 + 0][ra] = pb.x; Bs[nb][wq * 4 + 1][ra] = pb.y;
            Bs[nb][wq * 4 + 2][ra] = pb.z; Bs[nb][wq * 4 + 3][ra] = pb.w;
        }
        __syncthreads();
    }

    // epilogue: v = 4096 - 2*acc + sb[col], write short, fused stats
    int sbr[4];
#pragma unroll
    for (int j = 0; j < 4; j++) {
        int col = col0 + tx * 4 + j;
        sbr[j] = (col < L1N) ? sb[col] : 0;
    }
    int s_loc[4];
    unsigned q_loc[4];
#pragma unroll
    for (int j = 0; j < 4; j++) { s_loc[j] = 0; q_loc[j] = 0; }
#pragma unroll
    for (int i = 0; i < 8; i++) {
        int row = row0 + ty * 8 + i;
#pragma unroll
        for (int j = 0; j < 4; j++) {
            int col = col0 + tx * 4 + j;
            int v = 4096 - 2 * acc[i][j] + sbr[j];
            if (col < L1N) out[(size_t)row * L1N + col] = (short)v;
            s_loc[j] += v;
            q_loc[j] += (unsigned)(v * v);
        }
    }
    // block tree-reduce over ty (16), reuse smem
    int* Ssum = (int*)&As[0][0][0];        // [16][64]
    unsigned* Ssq = (unsigned*)&Bs[0][0][0];
#pragma unroll
    for (int j = 0; j < 4; j++) {
        Ssum[ty * 64 + tx * 4 + j] = s_loc[j];
        Ssq [ty * 64 + tx * 4 + j] = q_loc[j];
    }
    __syncthreads();
    for (int off = 8; off >= 1; off >>= 1) {
        if (ty < off) {
#pragma unroll
            for (int j = 0; j < 4; j++) {
                int c = tx * 4 + j;
                Ssum[ty * 64 + c] += Ssum[(ty + off) * 64 + c];
                Ssq [ty * 64 + c] += Ssq [(ty + off) * 64 + c];
            }
        }
        __syncthreads();
    }
    if (ty == 0) {
#pragma unroll
        for (int j = 0; j < 4; j++) {
            int col = col0 + tx * 4 + j;
            if (col < L1N) {
                atomicAdd(&g_sum[col], Ssum[tx * 4 + j]);
                atomicAdd(&g_sum2[col], (unsigned long long)Ssq[tx * 4 + j]);
            }
        }
    }
}

// ---------------- generic xor-popcount GEMM (small layers), fused stats ----------------
template <bool FINAL>
__global__ void __launch_bounds__(256)
gemm_popc_kernel(const unsigned* __restrict__ abits, const unsigned* __restrict__ bbits,
                 const int* __restrict__ sb, short* __restrict__ aout,
                 float* __restrict__ fout, int N, int K, int KW, int one) {
    __shared__ unsigned As[64][17];
    __shared__ unsigned Bs[16][64];

    const int tx = threadIdx.x & 15;
    const int ty = threadIdx.x >> 4;
    const int row0 = blockIdx.y * 64;
    const int col0 = blockIdx.x * 64;

    int acc[4][4];
#pragma unroll
    for (int i = 0; i < 4; i++)
#pragma unroll
        for (int j = 0; j < 4; j++) acc[i][j] = 0;

    const int nchunks = (KW + 15) >> 4;
    for (int ch = 0; ch < nchunks; ch++) {
        const int w0 = ch * 16;
        for (int idx = threadIdx.x; idx < 64 * 16; idx += 256) {
            int r = idx >> 4, w = idx & 15;
            unsigned v = 0;
            if (w0 + w < KW) v = abits[(size_t)(row0 + r) * KW + w0 + w];
            As[r][w] = v;
        }
        for (int idx = threadIdx.x; idx < 64 * 16; idx += 256) {
            int c = idx & 63, w = idx >> 6;
            unsigned v = 0;
            int col = col0 + c;
            if (col < N && w0 + w < KW) v = bbits[(size_t)col * KW + w0 + w];
            Bs[w][c] = v;
        }
        __syncthreads();
#pragma unroll
        for (int w = 0; w < 16; w++) {
            unsigned a0 = As[ty * 4 + 0][w];
            unsigned a1 = As[ty * 4 + 1][w];
            unsigned a2 = As[ty * 4 + 2][w];
            unsigned a3 = As[ty * 4 + 3][w];
            uint4 bv = *(const uint4*)&Bs[w][tx * 4];
            acc[0][0] += __popc(a0 ^ bv.x) * one; acc[0][1] += __popc(a0 ^ bv.y) * one;
            acc[0][2] += __popc(a0 ^ bv.z) * one; acc[0][3] += __popc(a0 ^ bv.w) * one;
            acc[1][0] += __popc(a1 ^ bv.x) * one; acc[1][1] += __popc(a1 ^ bv.y) * one;
            acc[1][2] += __popc(a1 ^ bv.z) * one; acc[1][3] += __popc(a1 ^ bv.w) * one;
            acc[2][0] += __popc(a2 ^ bv.x) * one; acc[2][1] += __popc(a2 ^ bv.y) * one;
            acc[2][2] += __popc(a2 ^ bv.z) * one; acc[2][3] += __popc(a2 ^ bv.w) * one;
            acc[3][0] += __popc(a3 ^ bv.x) * one; acc[3][1] += __popc(a3 ^ bv.y) * one;
            acc[3][2] += __popc(a3 ^ bv.z) * one; acc[3][3] += __popc(a3 ^ bv.w) * one;
        }
        __syncthreads();
    }

    int s_loc[4];
    unsigned q_loc[4];
#pragma unroll
    for (int j = 0; j < 4; j++) { s_loc[j] = 0; q_loc[j] = 0; }
#pragma unroll
    for (int i = 0; i < 4; i++) {
        int row = row0 + ty * 4 + i;
#pragma unroll
        for (int j = 0; j < 4; j++) {
            int col = col0 + tx * 4 + j;
            int v = K - 2 * acc[i][j] + ((col < N) ? sb[col] : 0);
            if (col < N) {
                if (FINAL) fout[(size_t)row * N + col] = (float)v;
                else       aout[(size_t)row * N + col] = (short)v;
            }
            s_loc[j] += v;
            q_loc[j] += (unsigned)(v * v);
        }
    }
    if (!FINAL) {
        int* Ssum = (int*)&As[0][0];        // [16][64] fits in 64*17
        unsigned* Ssq = (unsigned*)&Bs[0][0];
        __syncthreads();   // ensure all smem reads of the mainloop are done (last chunk)
#pragma unroll
        for (int j = 0; j < 4; j++) {
            Ssum[ty * 64 + tx * 4 + j] = s_loc[j];
            Ssq [ty * 64 + tx * 4 + j] = q_loc[j];
        }
        __syncthreads();
        for (int off = 8; off >= 1; off >>= 1) {
            if (ty < off) {
#pragma unroll
                for (int j = 0; j < 4; j++) {
                    int c = tx * 4 + j;
                    Ssum[ty * 64 + c] += Ssum[(ty + off) * 64 + c];
                    Ssq [ty * 64 + c] += Ssq [(ty + off) * 64 + c];
                }
            }
            __syncthreads();
        }
        if (ty == 0) {
#pragma unroll
            for (int j = 0; j < 4; j++) {
                int col = col0 + tx * 4 + j;
                if (col < N) {
                    atomicAdd(&g_sum[col], Ssum[tx * 4 + j]);
                    atomicAdd(&g_sum2[col], (unsigned long long)Ssq[tx * 4 + j]);
                }
            }
        }
    }
}

// thresholds from stats (O(N) doubles, once per layer), then zero stats for next layer.
__global__ void params_kernel(const float* __restrict__ gam, const float* __restrict__ bet, int N) {
    int j = blockIdx.x * blockDim.x + threadIdx.x;
    if (j >= N) return;
    double mean = (double)g_sum[j] / 16384.0;
    double var  = (double)(long long)g_sum2[j] / 16384.0 - mean * mean;
    double invstd = 1.0 / sqrt(var + 1e-5);
    double scale = invstd * (double)gam[j];
    double shift = (double)bet[j];
    int thr, mode;
    if (scale > 0.0) {
        double t = mean - shift / scale;
        t = fmin(fmax(t, -1.0e9), 1.0e9);
        thr = (int)ceil(t);  mode = 0;            // neg = a < thr
    } else if (scale < 0.0) {
        double t = mean - shift / scale;
        t = fmin(fmax(t, -1.0e9), 1.0e9);
        thr = (int)floor(t); mode = 1;            // neg = a > thr
    } else {
        mode = 0;
        thr = (shift < 0.0) ? 2147483647 : (-2147483647 - 1);
    }
    g_thr[j] = thr;
    g_mode[j] = mode;
    g_sum[j] = 0;          // ready for next layer
    g_sum2[j] = 0ull;
}

// ---------------- pack next-layer sign bits: pure integer compare ----------------
__global__ void pack_act_kernel(const short* __restrict__ a, unsigned* __restrict__ dst,
                                int C, int KW) {
    int warp = (int)((blockIdx.x * blockDim.x + threadIdx.x) >> 5);
    int lane = threadIdx.x & 31;
    if (warp >= MB * KW) return;
    int row = warp / KW;
    int word = warp - row * KW;
    int col = word * 32 + lane;
    bool neg = false;
    if (col < C) {
        int v = a[(size_t)row * C + col];
        int thr = g_thr[col];
        neg = g_mode[col] ? (v > thr) : (v < thr);
    }
    unsigned mask = __ballot_sync(0xffffffffu, neg);
    if (lane == 0) dst[(size_t)row * KW + word] = mask;
}

// ---------------- host orchestration ----------------
extern "C" void kernel_launch(void* const* d_in, const int* in_sizes, int n_in,
                              void* d_out, int out_size) {
    (void)in_sizes; (void)n_in; (void)out_size;
    static const int LK[6]  = {4096, 500, 400, 350, 300, 300};
    static const int LN[6]  = {500, 400, 350, 300, 300, 35};
    static const int LKW[6] = {128, 16, 13, 11, 10, 10};

    const float* x = (const float*)d_in[0];
    const float* W[6]; const float* bb[6]; const float* gam[5]; const float* bet[5];
    for (int l = 0; l < 5; l++) {
        W[l]   = (const float*)d_in[1 + 4 * l];
        bb[l]  = (const float*)d_in[2 + 4 * l];
        gam[l] = (const float*)d_in[3 + 4 * l];
        bet[l] = (const float*)d_in[4 + 4 * l];
    }
    W[5]  = (const float*)d_in[21];
    bb[5] = (const float*)d_in[22];

    unsigned *act0, *act1, *wb;
    int *sb;
    short *aout;
    cudaGetSymbolAddress((void**)&act0, g_act0);
    cudaGetSymbolAddress((void**)&act1, g_act1);
    cudaGetSymbolAddress((void**)&wb,   g_wb);
    cudaGetSymbolAddress((void**)&sb,   g_sb);
    cudaGetSymbolAddress((void**)&aout, g_aout);

    // gemm1 must be the 4th launch (ncu capture position).
    pack_sign_kernel<<<(MB * 128 + 7) / 8, 256>>>(x, act0, MB, 4096, 128);               // 1
    pack_sign_kernel<<<(LN[0] * LKW[0] + 7) / 8, 256>>>(W[0], wb, LN[0], LK[0], LKW[0]); // 2
    pack_b_kernel<<<1, 512>>>(bb[0], sb, LN[0], 1);                                      // 3 (+zero stats)
    {                                                                                    // 4: gemm1 + stats
        dim3 grid(8, MB / 128);
        gemm1_kernel<<<grid, 256>>>(act0, wb, sb, aout, 1);
    }
    for (int l = 1; l < 6; l++) {
        pack_sign_kernel<<<(LN[l] * LKW[l] + 7) / 8, 256>>>(W[l], wb + (size_t)l * 64000,
                                                            LN[l], LK[l], LKW[l]);
        pack_b_kernel<<<2, 256>>>(bb[l], sb + l * 512, LN[l], 0);
    }
    params_kernel<<<2, 256>>>(gam[0], bet[0], LN[0]);
    pack_act_kernel<<<(MB * LKW[1] + 7) / 8, 256>>>(aout, act1, LN[0], LKW[1]);

    unsigned* actIn = act1;
    for (int l = 1; l < 5; l++) {
        const int N = LN[l], K = LK[l], KW = LKW[l];
        dim3 grid((N + 63) / 64, MB / 64);
        gemm_popc_kernel<false><<<grid, 256>>>(actIn, wb + (size_t)l * 64000,
                                               sb + l * 512, aout, nullptr, N, K, KW, 1);
        params_kernel<<<2, 256>>>(gam[l], bet[l], N);
        unsigned* actOut = (l % 2 == 0) ? act1 : act0;
        int KWn = LKW[l + 1];
        pack_act_kernel<<<(MB * KWn + 7) / 8, 256>>>(aout, actOut, N, KWn);
        actIn = actOut;
    }
    // final classifier -> fp32 output (exact integers), no stats
    {
        const int N = LN[5], K = LK[5], KW = LKW[5];
        dim3 grid((N + 63) / 64, MB / 64);
        gemm_popc_kernel<true><<<grid, 256>>>(actIn, wb + (size_t)5 * 64000,
                                              sb + 5 * 512, nullptr, (float*)d_out, N, K, KW, 1);
    }
}